// round 16
// baseline (speedup 1.0000x reference)
#include <cuda_runtime.h>
#include <cuda_fp16.h>
#include <cstdint>

#define NT 4096      // tokens B*S
#define HD 1024      // hidden dim
#define ID 2048      // intermediate dim
#define NE 8         // experts
#define NP 8192      // NT * TOPK

#define KCH2  64     // K chunk (both GEMMs)
#define SKP2  72     // fp16 row stride for 64-K tiles (144 B, conflict-free)

// ---------------- static device scratch ----------------
__device__ int d_cnt[NE];
__device__ int d_list[NE][NP];

__device__ __align__(16) __half d_x16[(size_t)NT * HD];
__device__ __align__(16) __half d_g16[(size_t)NE * ID * HD];
__device__ __align__(16) __half d_u16[(size_t)NE * ID * HD];
__device__ __align__(16) __half d_d16[(size_t)NE * HD * ID];
__device__ __align__(16) __half d_h16[(size_t)NP * ID];

// ---------------- PTX helpers ----------------
__device__ __forceinline__ uint32_t smem_u32(const void* p) {
    return (uint32_t)__cvta_generic_to_shared(p);
}
__device__ __forceinline__ void cp16(uint32_t dst, const void* src) {
    asm volatile("cp.async.cg.shared.global [%0], [%1], 16;\n" :: "r"(dst), "l"(src));
}
__device__ __forceinline__ void cp_commit() {
    asm volatile("cp.async.commit_group;\n");
}
template <int N>
__device__ __forceinline__ void cp_wait() {
    asm volatile("cp.async.wait_group %0;\n" :: "n"(N));
}
__device__ __forceinline__ void ldsm4(uint32_t r[4], uint32_t addr) {
    asm volatile("ldmatrix.sync.aligned.m8n8.x4.shared.b16 {%0,%1,%2,%3}, [%4];"
                 : "=r"(r[0]), "=r"(r[1]), "=r"(r[2]), "=r"(r[3]) : "r"(addr));
}
__device__ __forceinline__ void mma_f16(float c[4], const uint32_t a[4], const uint32_t b[2]) {
    asm volatile(
        "mma.sync.aligned.m16n8k16.row.col.f32.f16.f16.f32 "
        "{%0,%1,%2,%3}, {%4,%5,%6,%7}, {%8,%9}, {%0,%1,%2,%3};"
        : "+f"(c[0]), "+f"(c[1]), "+f"(c[2]), "+f"(c[3])
        : "r"(a[0]), "r"(a[1]), "r"(a[2]), "r"(a[3]), "r"(b[0]), "r"(b[1]));
}
__device__ __forceinline__ float silu_f(float v) { return v / (1.0f + __expf(-v)); }

__device__ __forceinline__ uint32_t pack_h2(float a, float b) {
    __half2 t;
    t.x = __float2half_rn(a);
    t.y = __float2half_rn(b);
    return *reinterpret_cast<uint32_t*>(&t);
}

// ---------------- kernel 1: routing (expert_indices is int32) ----------------
__global__ void k_route(const int* __restrict__ eidx) {
    int p = blockIdx.x * blockDim.x + threadIdx.x;
    if (p < NP) {
        int e = eidx[p];
        if (e >= 0 && e < NE) {
            int pos = atomicAdd(&d_cnt[e], 1);
            d_list[e][pos] = p;
        }
    }
}

// ---------------- merged convert + zero: x,g,u,d -> fp16; out -> 0; cnt -> 0 --
#define WN4 ((NE * ID * HD) / 4)
#define XN4 ((NT * HD) / 4)
#define ZN4 ((NT * HD) / 4)

__global__ void k_cvt_all(const float* __restrict__ x,  const float* __restrict__ g,
                          const float* __restrict__ u,  const float* __restrict__ d,
                          float* __restrict__ out) {
    if (blockIdx.x == 0 && threadIdx.x < NE) d_cnt[threadIdx.x] = 0;
    __half *x16 = d_x16, *g16 = d_g16, *u16 = d_u16, *d16 = d_d16;
    const long long total = 3LL * WN4 + XN4 + ZN4;
    long long i = (long long)blockIdx.x * blockDim.x + threadIdx.x;
    const long long stride = (long long)gridDim.x * blockDim.x;
    for (long long j = i; j < total; j += stride) {
        long long k = j;
        if (k >= 3LL * WN4 + XN4) {          // zero the output
            k -= 3LL * WN4 + XN4;
            reinterpret_cast<float4*>(out)[k] = make_float4(0.f, 0.f, 0.f, 0.f);
            continue;
        }
        const float4* s4;
        uint2* o2;
        if (k < WN4)                { s4 = (const float4*)g + k; o2 = (uint2*)g16 + k; }
        else if ((k -= WN4) < WN4)  { s4 = (const float4*)u + k; o2 = (uint2*)u16 + k; }
        else if ((k -= WN4) < WN4)  { s4 = (const float4*)d + k; o2 = (uint2*)d16 + k; }
        else { k -= WN4;              s4 = (const float4*)x + k; o2 = (uint2*)x16 + k; }
        float4 v = *s4;
        uint2 H;
        H.x = pack_h2(v.x, v.y);
        H.y = pack_h2(v.z, v.w);
        *o2 = H;
    }
}

// Map global m-tile (128 rows) to (expert, local tile).
__device__ __forceinline__ bool map_tile(int g, int* pe, int* pmt) {
    int e = -1, mt = 0;
#pragma unroll
    for (int ee = 0; ee < NE; ee++) {
        int nt = (d_cnt[ee] + 127) >> 7;
        if (e < 0) {
            if (g < nt) { e = ee; mt = g; }
            else g -= nt;
        }
    }
    *pe = e; *pmt = mt;
    return e >= 0;
}

// ======================================================================
// Kernel 2: gate/up GEMM (M=128, N=64, K=HD) fp16 MMA, K-chunk=64
// [R9/R15 config] 3-buffer ring; per buffer: A 0 (18432), Bg 18432 (9216),
// Bu 27648 (9216) = 36864 B.
// ======================================================================
#define GU_BUF 36864
#define GU_BG  18432
#define GU_BU  27648

__global__ void __launch_bounds__(256, 2)
k_gateup() {
    int e, mt;
    if (!map_tile(blockIdx.y, &e, &mt)) return;
    const int n_e = d_cnt[e];
    const int m0  = mt * 128;
    const int i0  = blockIdx.x * 64;

    extern __shared__ __align__(16) unsigned char smem[];
    const uint32_t sbase = smem_u32(smem);

    const int tid  = threadIdx.x;
    const int wid  = tid >> 5;
    const int lane = tid & 31;

    // ---- staging: 8 cp16/thread/chunk ----
    const int srow = tid >> 3;            // 0..31
    const int kl   = tid & 7;
    const __half* axp[4];
#pragma unroll
    for (int rp = 0; rp < 4; rp++) {
        int r = srow + 32 * rp;
        int p = (m0 + r < n_e) ? d_list[e][m0 + r] : d_list[e][m0];
        axp[rp] = d_x16 + (size_t)(p >> 1) * HD + kl * 8;
    }
    const __half *gp[2], *up[2];
#pragma unroll
    for (int rp = 0; rp < 2; rp++) {
        size_t wb = ((size_t)e * ID + i0 + srow + 32 * rp) * HD + kl * 8;
        gp[rp] = d_g16 + wb;
        up[rp] = d_u16 + wb;
    }

    // ---- fragment addresses (row stride 144 B) ----
    const int wm0 = (wid >> 1) * 32;
    const int wn0 = (wid & 1) * 32;
    const int lrA = lane & 15, lcA = lane >> 4;
    uint32_t aoff[2];
#pragma unroll
    for (int fm = 0; fm < 2; fm++)
        aoff[fm] = (uint32_t)((wm0 + fm * 16 + lrA) * (SKP2 * 2) + lcA * 16);
    const int mi = lane >> 3;
    const int bn = ((mi >> 1) << 3) + (lane & 7);
    const int bk = (mi & 1) << 3;
    uint32_t boff4[2];
#pragma unroll
    for (int q = 0; q < 2; q++)
        boff4[q] = (uint32_t)((wn0 + q * 16 + bn) * (SKP2 * 2) + bk * 2);

    float cg[2][4][4] = {};
    float cu[2][4][4] = {};

    auto stage = [&](int ic) {
        uint32_t B0 = sbase + (uint32_t)(ic % 3) * GU_BUF;
        int kc = ic * KCH2;
#pragma unroll
        for (int rp = 0; rp < 4; rp++)
            cp16(B0 + (uint32_t)((srow + 32 * rp) * (SKP2 * 2) + kl * 16), axp[rp] + kc);
#pragma unroll
        for (int rp = 0; rp < 2; rp++) {
            uint32_t d = B0 + (uint32_t)((srow + 32 * rp) * (SKP2 * 2) + kl * 16);
            cp16(d + GU_BG, gp[rp] + kc);
            cp16(d + GU_BU, up[rp] + kc);
        }
    };

    stage(0); cp_commit();
    stage(1); cp_commit();

    const int nch = HD / KCH2;   // 16
    for (int ic = 0; ic < nch; ic++) {
        cp_wait<1>();
        __syncthreads();
        if (ic + 2 < nch) { stage(ic + 2); }
        cp_commit();
        const uint32_t B0 = sbase + (uint32_t)(ic % 3) * GU_BUF;

#pragma unroll
        for (int half = 0; half < 2; half++) {
            const uint32_t HB = B0 + half * 64;   // +32 K elems = +64 bytes
            uint32_t a[2][2][4];
#pragma unroll
            for (int fm = 0; fm < 2; fm++) {
                ldsm4(a[0][fm], HB + aoff[fm]);
                ldsm4(a[1][fm], HB + aoff[fm] + 32);
            }
#pragma unroll
            for (int h = 0; h < 2; h++) {
                const int ksb = h * 32;
                uint32_t bg[2][4], bu[2][4];
#pragma unroll
                for (int q = 0; q < 2; q++) {
                    ldsm4(bg[q], HB + GU_BG + boff4[q] + ksb);
                    ldsm4(bu[q], HB + GU_BU + boff4[q] + ksb);
                }
#pragma unroll
                for (int fm = 0; fm < 2; fm++)
#pragma unroll
                    for (int fn = 0; fn < 4; fn++) {
                        mma_f16(cg[fm][fn], a[h][fm], &bg[fn >> 1][(fn & 1) * 2]);
                        mma_f16(cu[fm][fn], a[h][fm], &bu[fn >> 1][(fn & 1) * 2]);
                    }
            }
        }
    }

    // ---- epilogue: h = silu(gate)*up -> fp16 ----
    const int g4  = lane >> 2;
    const int tig = lane & 3;
#pragma unroll
    for (int fm = 0; fm < 2; fm++) {
#pragma unroll
        for (int fn = 0; fn < 4; fn++) {
            int cc = wn0 + fn * 8 + tig * 2;
            int r0 = wm0 + fm * 16 + g4;
            int r1 = r0 + 8;
            float v00 = silu_f(cg[fm][fn][0]) * cu[fm][fn][0];
            float v01 = silu_f(cg[fm][fn][1]) * cu[fm][fn][1];
            float v10 = silu_f(cg[fm][fn][2]) * cu[fm][fn][2];
            float v11 = silu_f(cg[fm][fn][3]) * cu[fm][fn][3];
            if (m0 + r0 < n_e) {
                int p = d_list[e][m0 + r0];
                *reinterpret_cast<uint32_t*>(&d_h16[(size_t)p * ID + i0 + cc]) =
                    pack_h2(v00, v01);
            }
            if (m0 + r1 < n_e) {
                int p = d_list[e][m0 + r1];
                *reinterpret_cast<uint32_t*>(&d_h16[(size_t)p * ID + i0 + cc]) =
                    pack_h2(v10, v11);
            }
        }
    }
}

// ======================================================================
// Kernel 3: down GEMM (M=128, N=128, K=ID) fp16 MMA, K-chunk=64
// Warps 4(m) x 2(n), warp tile 32x64. 3-buffer ring;
// per buffer: A 0 (18432), B 18432 (18432) = 36864 B.
// ======================================================================
#define DN_BUF 36864
#define DN_B   18432

__global__ void __launch_bounds__(256, 2)
k_down(const float* __restrict__ ew, float* __restrict__ out) {
    int e, mt;
    if (!map_tile(blockIdx.y, &e, &mt)) return;
    const int n_e = d_cnt[e];
    const int m0  = mt * 128;
    const int n0  = blockIdx.x * 128;

    extern __shared__ __align__(16) unsigned char smem[];
    const uint32_t sbase = smem_u32(smem);

    const int tid  = threadIdx.x;
    const int wid  = tid >> 5;
    const int lane = tid & 31;

    // ---- staging: 8 cp16/thread/chunk ----
    const int srow = tid >> 3;            // 0..31
    const int kl   = tid & 7;
    const __half* ahp[4];
#pragma unroll
    for (int rp = 0; rp < 4; rp++) {
        int r = srow + 32 * rp;
        int p = (m0 + r < n_e) ? d_list[e][m0 + r] : d_list[e][m0];
        ahp[rp] = d_h16 + (size_t)p * ID + kl * 8;
    }
    const __half* bhp[4];
#pragma unroll
    for (int rp = 0; rp < 4; rp++)
        bhp[rp] = d_d16 + ((size_t)e * HD + n0 + srow + 32 * rp) * ID + kl * 8;

    // ---- fragment addresses: warps 4(m) x 2(n), warp tile m32 x n64 ----
    const int wm0 = (wid >> 1) * 32;
    const int wn0 = (wid & 1) * 64;
    const int lrA = lane & 15, lcA = lane >> 4;
    uint32_t aoff[2];
#pragma unroll
    for (int fm = 0; fm < 2; fm++)
        aoff[fm] = (uint32_t)((wm0 + fm * 16 + lrA) * (SKP2 * 2) + lcA * 16);
    const int mi = lane >> 3;
    const int bn = ((mi >> 1) << 3) + (lane & 7);
    const int bk = (mi & 1) << 3;
    uint32_t boff4[4];
#pragma unroll
    for (int q = 0; q < 4; q++)
        boff4[q] = (uint32_t)((wn0 + q * 16 + bn) * (SKP2 * 2) + bk * 2);

    float c[2][8][4] = {};

    auto stage = [&](int ic) {
        uint32_t B0 = sbase + (uint32_t)(ic % 3) * DN_BUF;
        int kc = ic * KCH2;
#pragma unroll
        for (int rp = 0; rp < 4; rp++) {
            uint32_t d = B0 + (uint32_t)((srow + 32 * rp) * (SKP2 * 2) + kl * 16);
            cp16(d, ahp[rp] + kc);
            cp16(d + DN_B, bhp[rp] + kc);
        }
    };

    stage(0); cp_commit();
    stage(1); cp_commit();

    const int nch = ID / KCH2;   // 32
    for (int ic = 0; ic < nch; ic++) {
        cp_wait<1>();
        __syncthreads();
        if (ic + 2 < nch) { stage(ic + 2); }
        cp_commit();
        const uint32_t B0 = sbase + (uint32_t)(ic % 3) * DN_BUF;

#pragma unroll
        for (int half = 0; half < 2; half++) {
            const uint32_t HB = B0 + half * 64;   // +32 K elems = +64 bytes
            uint32_t a[2][2][4];
#pragma unroll
            for (int fm = 0; fm < 2; fm++) {
                ldsm4(a[0][fm], HB + aoff[fm]);
                ldsm4(a[1][fm], HB + aoff[fm] + 32);
            }
#pragma unroll
            for (int h = 0; h < 2; h++) {
                const int ksb = h * 32;
                uint32_t bf[4][4];
#pragma unroll
                for (int q = 0; q < 4; q++)
                    ldsm4(bf[q], HB + DN_B + boff4[q] + ksb);
#pragma unroll
                for (int fm = 0; fm < 2; fm++)
#pragma unroll
                    for (int fn = 0; fn < 8; fn++)
                        mma_f16(c[fm][fn], a[h][fm], &bf[fn >> 1][(fn & 1) * 2]);
            }
        }
    }

    // ---- epilogue: weighted atomic scatter ----
    const int g4  = lane >> 2;
    const int tig = lane & 3;
#pragma unroll
    for (int fm = 0; fm < 2; fm++) {
        int r0 = wm0 + fm * 16 + g4;
        int r1 = r0 + 8;
        bool v0 = (m0 + r0 < n_e), v1 = (m0 + r1 < n_e);
        int p0 = v0 ? d_list[e][m0 + r0] : 0;
        int p1 = v1 ? d_list[e][m0 + r1] : 0;
        float w0 = v0 ? __ldg(&ew[p0]) : 0.0f;
        float w1 = v1 ? __ldg(&ew[p1]) : 0.0f;
        float* ob0 = out + (size_t)(p0 >> 1) * HD + n0;
        float* ob1 = out + (size_t)(p1 >> 1) * HD + n0;
#pragma unroll
        for (int fn = 0; fn < 8; fn++) {
            int cc = wn0 + fn * 8 + tig * 2;
            if (v0) {
                atomicAdd(ob0 + cc,     w0 * c[fm][fn][0]);
                atomicAdd(ob0 + cc + 1, w0 * c[fm][fn][1]);
            }
            if (v1) {
                atomicAdd(ob1 + cc,     w1 * c[fm][fn][2]);
                atomicAdd(ob1 + cc + 1, w1 * c[fm][fn][3]);
            }
        }
    }
}

// ---------------------------------------------------------------------------
extern "C" void kernel_launch(void* const* d_in, const int* in_sizes, int n_in,
                              void* d_out, int out_size) {
    const float* x    = (const float*)d_in[0];
    const int*   eidx = (const int*)d_in[1];
    const float* ew   = (const float*)d_in[2];
    const float* gw   = (const float*)d_in[3];
    const float* uw   = (const float*)d_in[4];
    const float* dw   = (const float*)d_in[5];
    float*       out  = (float*)d_out;

    cudaFuncSetAttribute(k_gateup, cudaFuncAttributeMaxDynamicSharedMemorySize, 3 * GU_BUF);
    cudaFuncSetAttribute(k_down,   cudaFuncAttributeMaxDynamicSharedMemorySize, 3 * DN_BUF);

    // cvt_all also zeroes out and d_cnt; it must precede k_route and the GEMMs.
    k_cvt_all<<<8192, 256>>>(x, gw, uw, dw, out);
    k_route<<<NP / 256, 256>>>(eidx);

    dim3 g1(ID / 64, 72);
    k_gateup<<<g1, 256, 3 * GU_BUF>>>();

    dim3 g2(HD / 128, 72);
    k_down<<<g2, 256, 3 * DN_BUF>>>(ew, out);
}

// round 17
// speedup vs baseline: 1.0070x; 1.0070x over previous
#include <cuda_runtime.h>
#include <cuda_fp16.h>
#include <cstdint>

#define NT 4096      // tokens B*S
#define HD 1024      // hidden dim
#define ID 2048      // intermediate dim
#define NE 8         // experts
#define NP 8192      // NT * TOPK

#define SKP   40     // fp16 row stride, 32-K tiles (down kernel)
#define KCH   32
#define SKP2  72     // fp16 row stride, 64-K tiles (gateup)
#define KCH2  64

// ---------------- static device scratch ----------------
__device__ int d_cnt[NE];
__device__ int d_list[NE][NP];

__device__ __align__(16) __half d_x16[(size_t)NT * HD];
__device__ __align__(16) __half d_g16[(size_t)NE * ID * HD];
__device__ __align__(16) __half d_u16[(size_t)NE * ID * HD];
__device__ __align__(16) __half d_d16[(size_t)NE * HD * ID];
__device__ __align__(16) __half d_h16[(size_t)NP * ID];

// ---------------- PTX helpers ----------------
__device__ __forceinline__ uint32_t smem_u32(const void* p) {
    return (uint32_t)__cvta_generic_to_shared(p);
}
__device__ __forceinline__ void cp16(uint32_t dst, const void* src) {
    asm volatile("cp.async.cg.shared.global [%0], [%1], 16;\n" :: "r"(dst), "l"(src));
}
__device__ __forceinline__ void cp_commit() {
    asm volatile("cp.async.commit_group;\n");
}
template <int N>
__device__ __forceinline__ void cp_wait() {
    asm volatile("cp.async.wait_group %0;\n" :: "n"(N));
}
__device__ __forceinline__ void ldsm4(uint32_t r[4], uint32_t addr) {
    asm volatile("ldmatrix.sync.aligned.m8n8.x4.shared.b16 {%0,%1,%2,%3}, [%4];"
                 : "=r"(r[0]), "=r"(r[1]), "=r"(r[2]), "=r"(r[3]) : "r"(addr));
}
__device__ __forceinline__ void mma_f16(float c[4], const uint32_t a[4], const uint32_t b[2]) {
    asm volatile(
        "mma.sync.aligned.m16n8k16.row.col.f32.f16.f16.f32 "
        "{%0,%1,%2,%3}, {%4,%5,%6,%7}, {%8,%9}, {%0,%1,%2,%3};"
        : "+f"(c[0]), "+f"(c[1]), "+f"(c[2]), "+f"(c[3])
        : "r"(a[0]), "r"(a[1]), "r"(a[2]), "r"(a[3]), "r"(b[0]), "r"(b[1]));
}
__device__ __forceinline__ float silu_f(float v) { return v / (1.0f + __expf(-v)); }

__device__ __forceinline__ uint32_t pack_h2(float a, float b) {
    __half2 t;
    t.x = __float2half_rn(a);
    t.y = __float2half_rn(b);
    return *reinterpret_cast<uint32_t*>(&t);
}

// ---------------- kernel 1: routing (expert_indices is int32) ----------------
__global__ void k_route(const int* __restrict__ eidx) {
    int p = blockIdx.x * blockDim.x + threadIdx.x;
    if (p < NP) {
        int e = eidx[p];
        if (e >= 0 && e < NE) {
            int pos = atomicAdd(&d_cnt[e], 1);
            d_list[e][pos] = p;
        }
    }
}

// ---------------- merged convert + zero: x,g,u,d -> fp16; out -> 0; cnt -> 0 --
#define WN4 ((NE * ID * HD) / 4)
#define XN4 ((NT * HD) / 4)
#define ZN4 ((NT * HD) / 4)

__global__ void k_cvt_all(const float* __restrict__ x,  const float* __restrict__ g,
                          const float* __restrict__ u,  const float* __restrict__ d,
                          float* __restrict__ out) {
    if (blockIdx.x == 0 && threadIdx.x < NE) d_cnt[threadIdx.x] = 0;
    __half *x16 = d_x16, *g16 = d_g16, *u16 = d_u16, *d16 = d_d16;
    const long long total = 3LL * WN4 + XN4 + ZN4;
    long long i = (long long)blockIdx.x * blockDim.x + threadIdx.x;
    const long long stride = (long long)gridDim.x * blockDim.x;
    for (long long j = i; j < total; j += stride) {
        long long k = j;
        if (k >= 3LL * WN4 + XN4) {          // zero the output
            k -= 3LL * WN4 + XN4;
            reinterpret_cast<float4*>(out)[k] = make_float4(0.f, 0.f, 0.f, 0.f);
            continue;
        }
        const float4* s4;
        uint2* o2;
        if (k < WN4)                { s4 = (const float4*)g + k; o2 = (uint2*)g16 + k; }
        else if ((k -= WN4) < WN4)  { s4 = (const float4*)u + k; o2 = (uint2*)u16 + k; }
        else if ((k -= WN4) < WN4)  { s4 = (const float4*)d + k; o2 = (uint2*)d16 + k; }
        else { k -= WN4;              s4 = (const float4*)x + k; o2 = (uint2*)x16 + k; }
        float4 v = *s4;
        uint2 H;
        H.x = pack_h2(v.x, v.y);
        H.y = pack_h2(v.z, v.w);
        *o2 = H;
    }
}

// Map global m-tile (128 rows) to (expert, local tile).
__device__ __forceinline__ bool map_tile(int g, int* pe, int* pmt) {
    int e = -1, mt = 0;
#pragma unroll
    for (int ee = 0; ee < NE; ee++) {
        int nt = (d_cnt[ee] + 127) >> 7;
        if (e < 0) {
            if (g < nt) { e = ee; mt = g; }
            else g -= nt;
        }
    }
    *pe = e; *pmt = mt;
    return e >= 0;
}

// ======================================================================
// Kernel 2: gate/up GEMM (M=128, N=64, K=HD) fp16 MMA, K-chunk=64
// [R9 config: measured 228us] 3-buffer ring; per buffer: A 0 (18432),
// Bg 18432 (9216), Bu 27648 (9216) = 36864 B.
// ======================================================================
#define GU_BUF 36864
#define GU_BG  18432
#define GU_BU  27648

__global__ void __launch_bounds__(256, 2)
k_gateup() {
    int e, mt;
    if (!map_tile(blockIdx.y, &e, &mt)) return;
    const int n_e = d_cnt[e];
    const int m0  = mt * 128;
    const int i0  = blockIdx.x * 64;

    extern __shared__ __align__(16) unsigned char smem[];
    const uint32_t sbase = smem_u32(smem);

    const int tid  = threadIdx.x;
    const int wid  = tid >> 5;
    const int lane = tid & 31;

    // ---- staging: 8 cp16/thread/chunk ----
    const int srow = tid >> 3;            // 0..31
    const int kl   = tid & 7;
    const __half* axp[4];
#pragma unroll
    for (int rp = 0; rp < 4; rp++) {
        int r = srow + 32 * rp;
        int p = (m0 + r < n_e) ? d_list[e][m0 + r] : d_list[e][m0];
        axp[rp] = d_x16 + (size_t)(p >> 1) * HD + kl * 8;
    }
    const __half *gp[2], *up[2];
#pragma unroll
    for (int rp = 0; rp < 2; rp++) {
        size_t wb = ((size_t)e * ID + i0 + srow + 32 * rp) * HD + kl * 8;
        gp[rp] = d_g16 + wb;
        up[rp] = d_u16 + wb;
    }

    // ---- fragment addresses (row stride 144 B) ----
    const int wm0 = (wid >> 1) * 32;
    const int wn0 = (wid & 1) * 32;
    const int lrA = lane & 15, lcA = lane >> 4;
    uint32_t aoff[2];
#pragma unroll
    for (int fm = 0; fm < 2; fm++)
        aoff[fm] = (uint32_t)((wm0 + fm * 16 + lrA) * (SKP2 * 2) + lcA * 16);
    const int mi = lane >> 3;
    const int bn = ((mi >> 1) << 3) + (lane & 7);
    const int bk = (mi & 1) << 3;
    uint32_t boff4[2];
#pragma unroll
    for (int q = 0; q < 2; q++)
        boff4[q] = (uint32_t)((wn0 + q * 16 + bn) * (SKP2 * 2) + bk * 2);

    float cg[2][4][4] = {};
    float cu[2][4][4] = {};

    auto stage = [&](int ic) {
        uint32_t B0 = sbase + (uint32_t)(ic % 3) * GU_BUF;
        int kc = ic * KCH2;
#pragma unroll
        for (int rp = 0; rp < 4; rp++)
            cp16(B0 + (uint32_t)((srow + 32 * rp) * (SKP2 * 2) + kl * 16), axp[rp] + kc);
#pragma unroll
        for (int rp = 0; rp < 2; rp++) {
            uint32_t d = B0 + (uint32_t)((srow + 32 * rp) * (SKP2 * 2) + kl * 16);
            cp16(d + GU_BG, gp[rp] + kc);
            cp16(d + GU_BU, up[rp] + kc);
        }
    };

    stage(0); cp_commit();
    stage(1); cp_commit();

    const int nch = HD / KCH2;   // 16
    for (int ic = 0; ic < nch; ic++) {
        cp_wait<1>();
        __syncthreads();
        if (ic + 2 < nch) { stage(ic + 2); }
        cp_commit();
        const uint32_t B0 = sbase + (uint32_t)(ic % 3) * GU_BUF;

#pragma unroll
        for (int half = 0; half < 2; half++) {
            const uint32_t HB = B0 + half * 64;   // +32 K elems = +64 bytes
            uint32_t a[2][2][4];
#pragma unroll
            for (int fm = 0; fm < 2; fm++) {
                ldsm4(a[0][fm], HB + aoff[fm]);
                ldsm4(a[1][fm], HB + aoff[fm] + 32);
            }
#pragma unroll
            for (int h = 0; h < 2; h++) {
                const int ksb = h * 32;
                uint32_t bg[2][4], bu[2][4];
#pragma unroll
                for (int q = 0; q < 2; q++) {
                    ldsm4(bg[q], HB + GU_BG + boff4[q] + ksb);
                    ldsm4(bu[q], HB + GU_BU + boff4[q] + ksb);
                }
#pragma unroll
                for (int fm = 0; fm < 2; fm++)
#pragma unroll
                    for (int fn = 0; fn < 4; fn++) {
                        mma_f16(cg[fm][fn], a[h][fm], &bg[fn >> 1][(fn & 1) * 2]);
                        mma_f16(cu[fm][fn], a[h][fm], &bu[fn >> 1][(fn & 1) * 2]);
                    }
            }
        }
    }

    // ---- epilogue: h = silu(gate)*up -> fp16 ----
    const int g4  = lane >> 2;
    const int tig = lane & 3;
#pragma unroll
    for (int fm = 0; fm < 2; fm++) {
#pragma unroll
        for (int fn = 0; fn < 4; fn++) {
            int cc = wn0 + fn * 8 + tig * 2;
            int r0 = wm0 + fm * 16 + g4;
            int r1 = r0 + 8;
            float v00 = silu_f(cg[fm][fn][0]) * cu[fm][fn][0];
            float v01 = silu_f(cg[fm][fn][1]) * cu[fm][fn][1];
            float v10 = silu_f(cg[fm][fn][2]) * cu[fm][fn][2];
            float v11 = silu_f(cg[fm][fn][3]) * cu[fm][fn][3];
            if (m0 + r0 < n_e) {
                int p = d_list[e][m0 + r0];
                *reinterpret_cast<uint32_t*>(&d_h16[(size_t)p * ID + i0 + cc]) =
                    pack_h2(v00, v01);
            }
            if (m0 + r1 < n_e) {
                int p = d_list[e][m0 + r1];
                *reinterpret_cast<uint32_t*>(&d_h16[(size_t)p * ID + i0 + cc]) =
                    pack_h2(v10, v11);
            }
        }
    }
}

// ======================================================================
// Kernel 3: down GEMM (M=128, N=128, K=ID) fp16 MMA  [R13 config: 117.3us]
// Warps 4(m) x 2(n), warp tile 32x64. 4-stage ring;
// per buffer: A 0 (10240), B 10240 (10240) = 20480.
// ======================================================================
#define DN_BUF 20480
#define DN_B   10240

__global__ void __launch_bounds__(256, 2)
k_down(const float* __restrict__ ew, float* __restrict__ out) {
    int e, mt;
    if (!map_tile(blockIdx.y, &e, &mt)) return;
    const int n_e = d_cnt[e];
    const int m0  = mt * 128;
    const int n0  = blockIdx.x * 128;

    extern __shared__ __align__(16) unsigned char smem[];
    const uint32_t sbase = smem_u32(smem);

    const int tid  = threadIdx.x;
    const int wid  = tid >> 5;
    const int lane = tid & 31;

    // ---- staging: 4 cp16/thread/chunk ----
    const int sr = tid >> 2;      // 0..63
    const int sc = tid & 3;
    const __half* ahp[2];
#pragma unroll
    for (int rp = 0; rp < 2; rp++) {
        int r = sr + rp * 64;
        int p = (m0 + r < n_e) ? d_list[e][m0 + r] : d_list[e][m0];
        ahp[rp] = d_h16 + (size_t)p * ID + sc * 8;
    }
    const __half* bhp[2];
#pragma unroll
    for (int rp = 0; rp < 2; rp++)
        bhp[rp] = d_d16 + ((size_t)e * HD + n0 + sr + rp * 64) * ID + sc * 8;

    const uint32_t adst = (uint32_t)(sr * (SKP * 2) + sc * 16);

    // ---- fragment addresses: warps 4(m) x 2(n), warp tile m32 x n64 ----
    const int wm0 = (wid >> 1) * 32;
    const int wn0 = (wid & 1) * 64;
    const int lrA = lane & 15, lcA = lane >> 4;
    uint32_t aoff[2];
#pragma unroll
    for (int fm = 0; fm < 2; fm++)
        aoff[fm] = (uint32_t)(((wm0 + fm * 16 + lrA) * SKP + lcA * 8) * 2);
    const int mi = lane >> 3;
    const int bn = ((mi >> 1) << 3) + (lane & 7);
    const int bk = (mi & 1) << 3;
    uint32_t boff4[4];
#pragma unroll
    for (int q = 0; q < 4; q++)
        boff4[q] = (uint32_t)(((wn0 + q * 16 + bn) * SKP + bk) * 2);

    float c[2][8][4] = {};

    auto stage = [&](int ic) {
        uint32_t B0 = sbase + (uint32_t)(ic & 3) * DN_BUF;
        int kc = ic * KCH;
#pragma unroll
        for (int rp = 0; rp < 2; rp++) {
            cp16(B0 + adst + (uint32_t)rp * 64 * (SKP * 2), ahp[rp] + kc);
            cp16(B0 + DN_B + adst + (uint32_t)rp * 64 * (SKP * 2), bhp[rp] + kc);
        }
    };

    stage(0); cp_commit();
    stage(1); cp_commit();
    stage(2); cp_commit();

    const int nch = ID / KCH;   // 64
    for (int ic = 0; ic < nch; ic++) {
        cp_wait<2>();
        __syncthreads();
        if (ic + 3 < nch) { stage(ic + 3); }
        cp_commit();
        const uint32_t B0 = sbase + (uint32_t)(ic & 3) * DN_BUF;

        uint32_t a[2][2][4];
#pragma unroll
        for (int fm = 0; fm < 2; fm++) {
            ldsm4(a[0][fm], B0 + aoff[fm]);
            ldsm4(a[1][fm], B0 + aoff[fm] + 32);
        }
#pragma unroll
        for (int h = 0; h < 2; h++) {
            const int ksb = h * 32;
            uint32_t bf[4][4];
#pragma unroll
            for (int q = 0; q < 4; q++)
                ldsm4(bf[q], B0 + DN_B + boff4[q] + ksb);
#pragma unroll
            for (int fm = 0; fm < 2; fm++)
#pragma unroll
                for (int fn = 0; fn < 8; fn++)
                    mma_f16(c[fm][fn], a[h][fm], &bf[fn >> 1][(fn & 1) * 2]);
        }
    }

    // ---- epilogue: weighted atomic scatter ----
    const int g4  = lane >> 2;
    const int tig = lane & 3;
#pragma unroll
    for (int fm = 0; fm < 2; fm++) {
        int r0 = wm0 + fm * 16 + g4;
        int r1 = r0 + 8;
        bool v0 = (m0 + r0 < n_e), v1 = (m0 + r1 < n_e);
        int p0 = v0 ? d_list[e][m0 + r0] : 0;
        int p1 = v1 ? d_list[e][m0 + r1] : 0;
        float w0 = v0 ? __ldg(&ew[p0]) : 0.0f;
        float w1 = v1 ? __ldg(&ew[p1]) : 0.0f;
        float* ob0 = out + (size_t)(p0 >> 1) * HD + n0;
        float* ob1 = out + (size_t)(p1 >> 1) * HD + n0;
#pragma unroll
        for (int fn = 0; fn < 8; fn++) {
            int cc = wn0 + fn * 8 + tig * 2;
            if (v0) {
                atomicAdd(ob0 + cc,     w0 * c[fm][fn][0]);
                atomicAdd(ob0 + cc + 1, w0 * c[fm][fn][1]);
            }
            if (v1) {
                atomicAdd(ob1 + cc,     w1 * c[fm][fn][2]);
                atomicAdd(ob1 + cc + 1, w1 * c[fm][fn][3]);
            }
        }
    }
}

// ---------------------------------------------------------------------------
extern "C" void kernel_launch(void* const* d_in, const int* in_sizes, int n_in,
                              void* d_out, int out_size) {
    const float* x    = (const float*)d_in[0];
    const int*   eidx = (const int*)d_in[1];
    const float* ew   = (const float*)d_in[2];
    const float* gw   = (const float*)d_in[3];
    const float* uw   = (const float*)d_in[4];
    const float* dw   = (const float*)d_in[5];
    float*       out  = (float*)d_out;

    cudaFuncSetAttribute(k_gateup, cudaFuncAttributeMaxDynamicSharedMemorySize, 3 * GU_BUF);
    cudaFuncSetAttribute(k_down,   cudaFuncAttributeMaxDynamicSharedMemorySize, 4 * DN_BUF);

    // cvt_all also zeroes out and d_cnt; it must precede k_route and the GEMMs.
    k_cvt_all<<<8192, 256>>>(x, gw, uw, dw, out);
    k_route<<<NP / 256, 256>>>(eidx);

    dim3 g1(ID / 64, 72);
    k_gateup<<<g1, 256, 3 * GU_BUF>>>();

    dim3 g2(HD / 128, 72);
    k_down<<<g2, 256, 4 * DN_BUF>>>(ew, out);
}